// round 14
// baseline (speedup 1.0000x reference)
#include <cuda_runtime.h>
#include <cuda_bf16.h>

#define N_ROWS 16384
#define DDIM   1024
#define GDIM   4096
#define DECAYF 0.97f
#define OMDEC  0.03f
#define INV_TEMP (1.0f/0.7f)
#define EPSF 1e-6f

#define P_OFF  67108864      // N_ROWS*GDIM
#define U_OFF  71303168      // P_OFF + GDIM*DDIM

// ---------------- device scratch (static; no allocations) ----------------
static __device__ __align__(16) __nv_bfloat16 g_qn[(size_t)N_ROWS * DDIM];     // normalized queries
static __device__ __align__(16) __nv_bfloat16 g_flatb[(size_t)N_ROWS * DDIM];  // flat * inv_rowsum (bf16)
static __device__ __align__(16) __nv_bfloat16 g_patn[(size_t)GDIM * DDIM];     // normalized patterns
static __device__ __align__(16) __nv_bfloat16 g_we[(size_t)N_ROWS * GDIM];     // exp logits (bf16, unnormalized)
static __device__ __align__(16) float g_upd[4][(size_t)GDIM * DDIM];           // split-K partials
static __device__ __align__(16) float g_rowpart[(size_t)32 * N_ROWS];          // per-gtile row sums (16 used)
static __device__ __align__(16) float g_colpart[(size_t)256 * GDIM];           // per-rowblock col sums
static __device__ __align__(16) float g_invrs[N_ROWS];                         // 1/rowsum
static __device__ __align__(16) float g_h[GDIM];
static __device__ __align__(16) float g_wsum[GDIM];
static __device__ float g_mstar;

// ---------------- helpers ----------------
__device__ __forceinline__ void mma16816(float* c, const unsigned* a, unsigned b0, unsigned b1) {
    asm volatile(
        "mma.sync.aligned.m16n8k16.row.col.f32.bf16.bf16.f32 "
        "{%0,%1,%2,%3}, {%4,%5,%6,%7}, {%8,%9}, {%0,%1,%2,%3};\n"
        : "+f"(c[0]), "+f"(c[1]), "+f"(c[2]), "+f"(c[3])
        : "r"(a[0]), "r"(a[1]), "r"(a[2]), "r"(a[3]), "r"(b0), "r"(b1));
}

__device__ __forceinline__ void ldsm4(unsigned* r, unsigned addr) {
    asm volatile("ldmatrix.sync.aligned.m8n8.x4.shared.b16 {%0,%1,%2,%3}, [%4];"
        : "=r"(r[0]), "=r"(r[1]), "=r"(r[2]), "=r"(r[3]) : "r"(addr));
}

__device__ __forceinline__ void ldsm4t(unsigned* r, unsigned addr) {
    asm volatile("ldmatrix.sync.aligned.m8n8.x4.trans.shared.b16 {%0,%1,%2,%3}, [%4];"
        : "=r"(r[0]), "=r"(r[1]), "=r"(r[2]), "=r"(r[3]) : "r"(addr));
}

__device__ __forceinline__ float block_sum_256(float v, float* sm8) {
    int t = threadIdx.x;
    #pragma unroll
    for (int o = 16; o > 0; o >>= 1) v += __shfl_xor_sync(0xffffffffu, v, o);
    if ((t & 31) == 0) sm8[t >> 5] = v;
    __syncthreads();
    float tot = 0.f;
    #pragma unroll
    for (int i = 0; i < 8; i++) tot += sm8[i];
    return tot;
}

// XOR-swizzled address inside a [rows][32 elems] bf16 tile (64B rows, 16B chunks)
__device__ __forceinline__ unsigned swz(unsigned base, int row, int chunk) {
    return base + (unsigned)(row * 64 + ((chunk ^ (row & 3)) << 4));
}

// ---------------- prep kernels ----------------
__global__ void __launch_bounds__(256) prep_rows(const float* __restrict__ pe) {
    int row = blockIdx.x, t = threadIdx.x;
    __shared__ float sm8[8];
    float4 v = ((const float4*)(pe + (size_t)row * DDIM))[t];
    float ss = v.x*v.x + v.y*v.y + v.z*v.z + v.w*v.w;
    float tot = block_sum_256(ss, sm8);
    float inv = 1.0f / fmaxf(sqrtf(tot), 1e-12f);
    size_t base = (size_t)row * DDIM + (size_t)t * 4;
    *(__nv_bfloat162*)&g_qn[base]     = __floats2bfloat162_rn(v.x*inv, v.y*inv);
    *(__nv_bfloat162*)&g_qn[base + 2] = __floats2bfloat162_rn(v.z*inv, v.w*inv);
}

__global__ void __launch_bounds__(256) prep_pat(const float* __restrict__ pat) {
    int row = blockIdx.x, t = threadIdx.x;
    __shared__ float sm8[8];
    float4 v = ((const float4*)(pat + (size_t)row * DDIM))[t];
    float ss = v.x*v.x + v.y*v.y + v.z*v.z + v.w*v.w;
    float tot = block_sum_256(ss, sm8);
    float inv = 1.0f / fmaxf(sqrtf(tot), 1e-12f);
    size_t base = (size_t)row * DDIM + (size_t)t * 4;
    *(__nv_bfloat162*)&g_patn[base]     = __floats2bfloat162_rn(v.x*inv, v.y*inv);
    *(__nv_bfloat162*)&g_patn[base + 2] = __floats2bfloat162_rn(v.z*inv, v.w*inv);
}

__global__ void __launch_bounds__(1024) prep_h(const float* __restrict__ usage) {
    int t = threadIdx.x;
    __shared__ float sm[32];
    float4 u = ((const float4*)usage)[t];
    float4 h;
    h.x = logf(fmaxf(u.x, EPSF)); h.y = logf(fmaxf(u.y, EPSF));
    h.z = logf(fmaxf(u.z, EPSF)); h.w = logf(fmaxf(u.w, EPSF));
    ((float4*)g_h)[t] = h;
    float m = fmaxf(fmaxf(1.f - h.x, 1.f - h.y), fmaxf(1.f - h.z, 1.f - h.w)) * INV_TEMP;
    #pragma unroll
    for (int o = 16; o > 0; o >>= 1) m = fmaxf(m, __shfl_xor_sync(0xffffffffu, m, o));
    if ((t & 31) == 0) sm[t >> 5] = m;
    __syncthreads();
    if (t == 0) {
        float mm = sm[0];
        #pragma unroll
        for (int i = 1; i < 32; i++) mm = fmaxf(mm, sm[i]);
        g_mstar = mm;
    }
}

// ---------------- GEMM1: 128(n) x 256(g) CTA tile, 512 thr, 64x32 warp tiles,
//                  cp.async double-buffered, XOR-swizzled smem, fused exp ----------------
#define STAGE_BYTES 24576   // A 8192 + B 16384
__global__ void __launch_bounds__(512, 1) gemm1_softmax(float* __restrict__ outW) {
    __shared__ __align__(16) char smbuf[2 * STAGE_BYTES];   // 48KB exactly
    int tid = threadIdx.x;
    int w = tid >> 5, lane = tid & 31;
    int wm = w >> 3, wn = w & 7;               // 2 x 8 warp grid, each 64x32
    int gr = lane >> 2, tig = lane & 3;
    int n0 = blockIdx.y * 128, g0 = blockIdx.x * 256;

    unsigned smb = (unsigned)__cvta_generic_to_shared(smbuf);

    // copy maps: A 512 chunks (1/thread), B 1024 chunks (2/thread)
    int ar = tid >> 2, au = tid & 3;
    int br0 = tid >> 2, bu0 = tid & 3;          // + j*128 rows

    float c[4][4][4];
    #pragma unroll
    for (int a = 0; a < 4; a++)
        #pragma unroll
        for (int b = 0; b < 4; b++)
            #pragma unroll
            for (int d = 0; d < 4; d++) c[a][b][d] = 0.f;

    // prologue: stage 0
    {
        unsigned ab = smb, bb = smb + 8192;
        const __nv_bfloat16* ga = &g_qn[(size_t)(n0 + ar) * DDIM + au * 8];
        asm volatile("cp.async.cg.shared.global [%0], [%1], 16;" :: "r"(swz(ab, ar, au)), "l"(ga));
        #pragma unroll
        for (int j = 0; j < 2; j++) {
            int r = j * 128 + br0;
            const __nv_bfloat16* gb = &g_patn[(size_t)(g0 + r) * DDIM + bu0 * 8];
            asm volatile("cp.async.cg.shared.global [%0], [%1], 16;" :: "r"(swz(bb, r, bu0)), "l"(gb));
        }
        asm volatile("cp.async.commit_group;");
    }

    for (int kt = 0; kt < 32; kt++) {
        int buf = kt & 1;
        if (kt < 31) {
            unsigned ab = smb + (buf ^ 1) * STAGE_BYTES, bb = ab + 8192;
            int k0 = (kt + 1) * 32;
            const __nv_bfloat16* ga = &g_qn[(size_t)(n0 + ar) * DDIM + k0 + au * 8];
            asm volatile("cp.async.cg.shared.global [%0], [%1], 16;" :: "r"(swz(ab, ar, au)), "l"(ga));
            #pragma unroll
            for (int j = 0; j < 2; j++) {
                int r = j * 128 + br0;
                const __nv_bfloat16* gb = &g_patn[(size_t)(g0 + r) * DDIM + k0 + bu0 * 8];
                asm volatile("cp.async.cg.shared.global [%0], [%1], 16;" :: "r"(swz(bb, r, bu0)), "l"(gb));
            }
            asm volatile("cp.async.commit_group;");
            asm volatile("cp.async.wait_group 1;");
        } else {
            asm volatile("cp.async.wait_group 0;");
        }
        __syncthreads();

        unsigned ab = smb + buf * STAGE_BYTES, bb = ab + 8192;
        #pragma unroll
        for (int ks = 0; ks < 2; ks++) {
            unsigned a[4][4];
            #pragma unroll
            for (int mt = 0; mt < 4; mt++)
                ldsm4(a[mt], swz(ab, wm * 64 + mt * 16 + (lane & 15), 2 * ks + (lane >> 4)));
            #pragma unroll
            for (int nt2 = 0; nt2 < 2; nt2++) {
                unsigned b[4];
                ldsm4(b, swz(bb, wn * 32 + nt2 * 16 + ((lane >> 4) << 3) + (lane & 7),
                             2 * ks + ((lane >> 3) & 1)));
                #pragma unroll
                for (int mt = 0; mt < 4; mt++) {
                    mma16816(c[mt][nt2 * 2],     a[mt], b[0], b[1]);
                    mma16816(c[mt][nt2 * 2 + 1], a[mt], b[2], b[3]);
                }
            }
        }
        __syncthreads();
    }

    // epilogue
    float mst = g_mstar;
    float (*smrow)[128] = (float (*)[128])smbuf;   // 8 x 128 floats, overlays dead A buffer
    #pragma unroll
    for (int mt = 0; mt < 4; mt++) {
        int r1 = wm * 64 + mt * 16 + gr, r2 = r1 + 8;
        float rs1 = 0.f, rs2 = 0.f;
        #pragma unroll
        for (int nt = 0; nt < 4; nt++) {
            int col = wn * 32 + nt * 8 + 2 * tig;
            float2 hh = *(const float2*)&g_h[g0 + col];
            float e0 = __expf((c[mt][nt][0] - hh.x) * INV_TEMP - mst);
            float e1 = __expf((c[mt][nt][1] - hh.y) * INV_TEMP - mst);
            float e2 = __expf((c[mt][nt][2] - hh.x) * INV_TEMP - mst);
            float e3 = __expf((c[mt][nt][3] - hh.y) * INV_TEMP - mst);
            size_t o1 = (size_t)(n0 + r1) * GDIM + g0 + col;
            size_t o2 = (size_t)(n0 + r2) * GDIM + g0 + col;
            *(float2*)&outW[o1] = make_float2(e0, e1);
            *(float2*)&outW[o2] = make_float2(e2, e3);
            *(__nv_bfloat162*)&g_we[o1] = __floats2bfloat162_rn(e0, e1);
            *(__nv_bfloat162*)&g_we[o2] = __floats2bfloat162_rn(e2, e3);
            rs1 += e0 + e1; rs2 += e2 + e3;
        }
        rs1 += __shfl_xor_sync(0xffffffffu, rs1, 1);
        rs1 += __shfl_xor_sync(0xffffffffu, rs1, 2);
        rs2 += __shfl_xor_sync(0xffffffffu, rs2, 1);
        rs2 += __shfl_xor_sync(0xffffffffu, rs2, 2);
        if (tig == 0) {
            if (mt == 0 && gr == 0) {}  // no-op
            smrow[wn][r1] = (mt == 0) ? rs1 : smrow[wn][r1];  // placeholder avoided below
        }
        if (tig == 0) { smrow[wn][r1] = rs1; smrow[wn][r2] = rs2; }
    }
    __syncthreads();
    if (tid < 128) {
        float s = 0.f;
        #pragma unroll
        for (int i = 0; i < 8; i++) s += smrow[i][tid];
        g_rowpart[(size_t)blockIdx.x * N_ROWS + n0 + tid] = s;
    }
}

// ---------------- rowsum reduce (16 g-tiles) + scale flat into bf16 ----------------
__global__ void __launch_bounds__(256) scale_flat(const float* __restrict__ pe) {
    int row = blockIdx.x, t = threadIdx.x;
    __shared__ float sinv;
    if (t < 32) {
        float v = (t < 16) ? g_rowpart[(size_t)t * N_ROWS + row] : 0.f;
        #pragma unroll
        for (int o = 8; o > 0; o >>= 1) v += __shfl_xor_sync(0xffffffffu, v, o);
        if (t == 0) {
            float iv = 1.0f / fmaxf(v, 1e-30f);
            g_invrs[row] = iv;
            sinv = iv;
        }
    }
    __syncthreads();
    float iv = sinv;
    float4 v = ((const float4*)(pe + (size_t)row * DDIM))[t];
    size_t base = (size_t)row * DDIM + (size_t)t * 4;
    *(__nv_bfloat162*)&g_flatb[base]     = __floats2bfloat162_rn(v.x*iv, v.y*iv);
    *(__nv_bfloat162*)&g_flatb[base + 2] = __floats2bfloat162_rn(v.z*iv, v.w*iv);
}

// ---------------- normalize W in place (fp32), emit column partials ----------------
__global__ void __launch_bounds__(256) normalize_k(float* __restrict__ W) {
    int tid = threadIdx.x;
    int c0 = blockIdx.x * 1024 + tid * 4;
    int r0 = blockIdx.y * 64;
    __shared__ float invs[64];
    if (tid < 64) invs[tid] = g_invrs[r0 + tid];
    __syncthreads();
    float cs0 = 0.f, cs1 = 0.f, cs2 = 0.f, cs3 = 0.f;
    for (int r = 0; r < 64; r++) {
        size_t off = (size_t)(r0 + r) * GDIM + c0;
        float4 e = *(float4*)&W[off];
        float iv = invs[r];
        e.x *= iv; e.y *= iv; e.z *= iv; e.w *= iv;
        *(float4*)&W[off] = e;
        cs0 += e.x; cs1 += e.y; cs2 += e.z; cs3 += e.w;
    }
    *(float4*)&g_colpart[(size_t)blockIdx.y * GDIM + c0] = make_float4(cs0, cs1, cs2, cs3);
}

// ---------------- GEMM2: updates = E^T @ flat_scaled, split-K=4, ldmatrix.trans ----------------
__global__ void __launch_bounds__(256) gemm2_k() {
    __shared__ __align__(16) __nv_bfloat16 As[32 * 136];
    __shared__ __align__(16) __nv_bfloat16 Bs[32 * 136];
    int tid = threadIdx.x;
    int w = tid >> 5, lane = tid & 31;
    int wm = w >> 1, wn = w & 1;
    int gr = lane >> 2, tig = lane & 3;
    int d0 = blockIdx.x * 128, g0 = blockIdx.y * 128;
    int kbase = blockIdx.z * 4096;

    unsigned as_base = (unsigned)__cvta_generic_to_shared(As);
    unsigned bs_base = (unsigned)__cvta_generic_to_shared(Bs);

    int a_k = (lane & 7) + ((lane >> 4) << 3);
    int a_m = ((lane >> 3) & 1) << 3;
    int b_k = (lane & 7) + (((lane >> 3) & 1) << 3);
    int b_d = (lane >> 4) << 3;

    int crow = tid >> 4;
    int cu = tid & 15;

    float c[2][8][4];
    #pragma unroll
    for (int a = 0; a < 2; a++)
        #pragma unroll
        for (int b = 0; b < 8; b++)
            #pragma unroll
            for (int d = 0; d < 4; d++) c[a][b][d] = 0.f;

    uint4 ra[2], rb[2];
    #pragma unroll
    for (int j = 0; j < 2; j++) {
        int row = j * 16 + crow;
        ra[j] = *(const uint4*)&g_we[(size_t)(kbase + row) * GDIM + g0 + cu * 8];
        rb[j] = *(const uint4*)&g_flatb[(size_t)(kbase + row) * DDIM + d0 + cu * 8];
    }

    for (int kt = 0; kt < 128; kt++) {
        #pragma unroll
        for (int j = 0; j < 2; j++) {
            int row = j * 16 + crow;
            *(uint4*)&As[row * 136 + cu * 8] = ra[j];
            *(uint4*)&Bs[row * 136 + cu * 8] = rb[j];
        }
        __syncthreads();
        if (kt < 127) {
            int k0 = kbase + (kt + 1) * 32;
            #pragma unroll
            for (int j = 0; j < 2; j++) {
                int row = j * 16 + crow;
                ra[j] = *(const uint4*)&g_we[(size_t)(k0 + row) * GDIM + g0 + cu * 8];
                rb[j] = *(const uint4*)&g_flatb[(size_t)(k0 + row) * DDIM + d0 + cu * 8];
            }
        }
        #pragma unroll
        for (int ks = 0; ks < 2; ks++) {
            unsigned a[2][4];
            #pragma unroll
            for (int mt = 0; mt < 2; mt++)
                ldsm4t(a[mt], as_base + (unsigned)(((ks * 16 + a_k) * 136 + wm * 32 + mt * 16 + a_m) * 2));
            #pragma unroll
            for (int nt2 = 0; nt2 < 4; nt2++) {
                unsigned b[4];
                ldsm4t(b, bs_base + (unsigned)(((ks * 16 + b_k) * 136 + wn * 64 + nt2 * 16 + b_d) * 2));
                #pragma unroll
                for (int mt = 0; mt < 2; mt++) {
                    mma16816(c[mt][nt2 * 2],     a[mt], b[0], b[1]);
                    mma16816(c[mt][nt2 * 2 + 1], a[mt], b[2], b[3]);
                }
            }
        }
        __syncthreads();
    }

    float* dst = g_upd[blockIdx.z];
    #pragma unroll
    for (int mt = 0; mt < 2; mt++) {
        int r1 = wm * 32 + mt * 16 + gr, r2 = r1 + 8;
        #pragma unroll
        for (int nt = 0; nt < 8; nt++) {
            int col = wn * 64 + nt * 8 + 2 * tig;
            *(float2*)&dst[(size_t)(g0 + r1) * DDIM + d0 + col] = make_float2(c[mt][nt][0], c[mt][nt][1]);
            *(float2*)&dst[(size_t)(g0 + r2) * DDIM + d0 + col] = make_float2(c[mt][nt][2], c[mt][nt][3]);
        }
    }
}

// ---------------- wsum reduction ----------------
__global__ void __launch_bounds__(256) wsum_reduce_k() {
    int g = blockIdx.x * 256 + threadIdx.x;
    float s = 0.f;
    for (int b = 0; b < 256; b++) s += g_colpart[(size_t)b * GDIM + g];
    g_wsum[g] = s;
}

// ---------------- final: blend, renormalize patterns, usage update ----------------
__global__ void __launch_bounds__(256) final_k(const float* __restrict__ patterns,
                                               const float* __restrict__ usage,
                                               float* __restrict__ out) {
    int g = blockIdx.x, t = threadIdx.x;
    __shared__ float sm8[8];
    size_t base = (size_t)g * DDIM + (size_t)t * 4;
    float4 r0 = *(const float4*)&g_upd[0][base];
    float4 r1 = *(const float4*)&g_upd[1][base];
    float4 r2 = *(const float4*)&g_upd[2][base];
    float4 r3 = *(const float4*)&g_upd[3][base];
    float4 raw;
    raw.x = (r0.x + r1.x) + (r2.x + r3.x);
    raw.y = (r0.y + r1.y) + (r2.y + r3.y);
    raw.z = (r0.z + r1.z) + (r2.z + r3.z);
    raw.w = (r0.w + r1.w) + (r2.w + r3.w);
    float ws = g_wsum[g];
    float sc = OMDEC / (ws + EPSF);
    float4 p = *(const float4*)&patterns[base];
    float4 v;
    v.x = p.x * DECAYF + raw.x * sc;
    v.y = p.y * DECAYF + raw.y * sc;
    v.z = p.z * DECAYF + raw.z * sc;
    v.w = p.w * DECAYF + raw.w * sc;
    float ss = v.x*v.x + v.y*v.y + v.z*v.z + v.w*v.w;
    float tot = block_sum_256(ss, sm8);
    float inv = 1.0f / fmaxf(sqrtf(tot), 1e-12f);
    bool valid = ws > 0.0f;
    float4 o;
    o.x = valid ? v.x * inv : p.x;
    o.y = valid ? v.y * inv : p.y;
    o.z = valid ? v.z * inv : p.z;
    o.w = valid ? v.w * inv : p.w;
    *(float4*)&out[(size_t)P_OFF + base] = o;
    if (t == 0)
        out[(size_t)U_OFF + g] = usage[g] * DECAYF + (valid ? OMDEC * ws : 0.0f);
}

// ---------------- launch ----------------
extern "C" void kernel_launch(void* const* d_in, const int* in_sizes, int n_in,
                              void* d_out, int out_size) {
    (void)in_sizes; (void)n_in; (void)out_size;
    const float* pe       = (const float*)d_in[0];
    const float* patterns = (const float*)d_in[1];
    const float* usage    = (const float*)d_in[2];
    float* out = (float*)d_out;

    prep_rows<<<N_ROWS, 256>>>(pe);
    prep_pat<<<GDIM, 256>>>(patterns);
    prep_h<<<1, 1024>>>(usage);
    gemm1_softmax<<<dim3(16, 128), 512>>>(out);
    scale_flat<<<N_ROWS, 256>>>(pe);
    gemm2_k<<<dim3(8, 32, 4), 256>>>();
    normalize_k<<<dim3(4, 256), 256>>>(out);
    wsum_reduce_k<<<16, 256>>>();
    final_k<<<GDIM, 256>>>(patterns, usage, out);
}

// round 15
// speedup vs baseline: 1.5814x; 1.5814x over previous
#include <cuda_runtime.h>
#include <cuda_bf16.h>

#define N_ROWS 16384
#define DDIM   1024
#define GDIM   4096
#define DECAYF 0.97f
#define OMDEC  0.03f
#define INV_TEMP (1.0f/0.7f)
#define EPSF 1e-6f

#define P_OFF  67108864      // N_ROWS*GDIM
#define U_OFF  71303168      // P_OFF + GDIM*DDIM

// ---------------- device scratch (static; no allocations) ----------------
static __device__ __align__(16) __nv_bfloat16 g_qn[(size_t)N_ROWS * DDIM];     // normalized queries
static __device__ __align__(16) __nv_bfloat16 g_flatb[(size_t)N_ROWS * DDIM];  // flat * inv_rowsum (bf16)
static __device__ __align__(16) __nv_bfloat16 g_patn[(size_t)GDIM * DDIM];     // normalized patterns
static __device__ __align__(16) __nv_bfloat16 g_we[(size_t)N_ROWS * GDIM];     // exp logits (bf16, unnormalized)
static __device__ __align__(16) float g_upd[4][(size_t)GDIM * DDIM];           // split-K partials
static __device__ __align__(16) float g_rowpart[(size_t)32 * N_ROWS];          // per-gtile row sums
static __device__ __align__(16) float g_colpart[(size_t)256 * GDIM];           // per-rowblock col sums
static __device__ __align__(16) float g_invrs[N_ROWS];                         // 1/rowsum
static __device__ __align__(16) float g_h[GDIM];
static __device__ __align__(16) float g_wsum[GDIM];
static __device__ float g_mstar;

// ---------------- helpers ----------------
__device__ __forceinline__ void mma16816(float* c, const unsigned* a, unsigned b0, unsigned b1) {
    asm volatile(
        "mma.sync.aligned.m16n8k16.row.col.f32.bf16.bf16.f32 "
        "{%0,%1,%2,%3}, {%4,%5,%6,%7}, {%8,%9}, {%0,%1,%2,%3};\n"
        : "+f"(c[0]), "+f"(c[1]), "+f"(c[2]), "+f"(c[3])
        : "r"(a[0]), "r"(a[1]), "r"(a[2]), "r"(a[3]), "r"(b0), "r"(b1));
}

__device__ __forceinline__ void ldsm4(unsigned* r, unsigned addr) {
    asm volatile("ldmatrix.sync.aligned.m8n8.x4.shared.b16 {%0,%1,%2,%3}, [%4];"
        : "=r"(r[0]), "=r"(r[1]), "=r"(r[2]), "=r"(r[3]) : "r"(addr));
}

__device__ __forceinline__ void ldsm4t(unsigned* r, unsigned addr) {
    asm volatile("ldmatrix.sync.aligned.m8n8.x4.trans.shared.b16 {%0,%1,%2,%3}, [%4];"
        : "=r"(r[0]), "=r"(r[1]), "=r"(r[2]), "=r"(r[3]) : "r"(addr));
}

__device__ __forceinline__ float block_sum_256(float v, float* sm8) {
    int t = threadIdx.x;
    #pragma unroll
    for (int o = 16; o > 0; o >>= 1) v += __shfl_xor_sync(0xffffffffu, v, o);
    if ((t & 31) == 0) sm8[t >> 5] = v;
    __syncthreads();
    float tot = 0.f;
    #pragma unroll
    for (int i = 0; i < 8; i++) tot += sm8[i];
    return tot;
}

// ---------------- prep kernels ----------------
__global__ void __launch_bounds__(256) prep_rows(const float* __restrict__ pe) {
    int row = blockIdx.x, t = threadIdx.x;
    __shared__ float sm8[8];
    float4 v = ((const float4*)(pe + (size_t)row * DDIM))[t];
    float ss = v.x*v.x + v.y*v.y + v.z*v.z + v.w*v.w;
    float tot = block_sum_256(ss, sm8);
    float inv = 1.0f / fmaxf(sqrtf(tot), 1e-12f);
    size_t base = (size_t)row * DDIM + (size_t)t * 4;
    *(__nv_bfloat162*)&g_qn[base]     = __floats2bfloat162_rn(v.x*inv, v.y*inv);
    *(__nv_bfloat162*)&g_qn[base + 2] = __floats2bfloat162_rn(v.z*inv, v.w*inv);
}

__global__ void __launch_bounds__(256) prep_pat(const float* __restrict__ pat) {
    int row = blockIdx.x, t = threadIdx.x;
    __shared__ float sm8[8];
    float4 v = ((const float4*)(pat + (size_t)row * DDIM))[t];
    float ss = v.x*v.x + v.y*v.y + v.z*v.z + v.w*v.w;
    float tot = block_sum_256(ss, sm8);
    float inv = 1.0f / fmaxf(sqrtf(tot), 1e-12f);
    size_t base = (size_t)row * DDIM + (size_t)t * 4;
    *(__nv_bfloat162*)&g_patn[base]     = __floats2bfloat162_rn(v.x*inv, v.y*inv);
    *(__nv_bfloat162*)&g_patn[base + 2] = __floats2bfloat162_rn(v.z*inv, v.w*inv);
}

__global__ void __launch_bounds__(1024) prep_h(const float* __restrict__ usage) {
    int t = threadIdx.x;
    __shared__ float sm[32];
    float4 u = ((const float4*)usage)[t];
    float4 h;
    h.x = logf(fmaxf(u.x, EPSF)); h.y = logf(fmaxf(u.y, EPSF));
    h.z = logf(fmaxf(u.z, EPSF)); h.w = logf(fmaxf(u.w, EPSF));
    ((float4*)g_h)[t] = h;
    float m = fmaxf(fmaxf(1.f - h.x, 1.f - h.y), fmaxf(1.f - h.z, 1.f - h.w)) * INV_TEMP;
    #pragma unroll
    for (int o = 16; o > 0; o >>= 1) m = fmaxf(m, __shfl_xor_sync(0xffffffffu, m, o));
    if ((t & 31) == 0) sm[t >> 5] = m;
    __syncthreads();
    if (t == 0) {
        float mm = sm[0];
        #pragma unroll
        for (int i = 1; i < 32; i++) mm = fmaxf(mm, sm[i]);
        g_mstar = mm;
    }
}

// ---------------- GEMM1: 128x128 CTA tile, 256 thr, 32x64 warp tiles,
//                  SA1=40 padded smem (conflict-free), cp.async double-buffered ----------------
#define SA1 40              // row stride (elems): 80B -> conflict-free (20r mod 32 banks)
#define OP_BYTES 10240      // 128 rows * 80B
#define STG_BYTES 20480     // A + B per stage
__global__ void __launch_bounds__(256) gemm1_softmax(float* __restrict__ outW) {
    __shared__ __align__(16) char smbuf[2 * STG_BYTES];   // 40KB
    __shared__ float smrow[2][128];
    int tid = threadIdx.x;
    int w = tid >> 5, lane = tid & 31;
    int wm = w >> 1, wn = w & 1;
    int gr = lane >> 2, tig = lane & 3;
    int n0 = blockIdx.y * 128, g0 = blockIdx.x * 128;

    unsigned smb = (unsigned)__cvta_generic_to_shared(smbuf);

    // ldmatrix lane maps (R7-verified)
    int a_row = lane & 15;
    int a_col = (lane >> 4) << 3;
    int b_row = ((lane >> 4) << 3) + (lane & 7);
    int b_col = ((lane >> 3) & 1) << 3;

    // copy map: 512 chunks of 16B per operand per k-tile; thread does 2 (r=lin>>2, u=lin&3)
    float c[2][8][4];
    #pragma unroll
    for (int a = 0; a < 2; a++)
        #pragma unroll
        for (int b = 0; b < 8; b++)
            #pragma unroll
            for (int d = 0; d < 4; d++) c[a][b][d] = 0.f;

    // prologue: stage 0
    {
        unsigned ab = smb, bb = smb + OP_BYTES;
        #pragma unroll
        for (int j = 0; j < 2; j++) {
            int lin = j * 256 + tid, r = lin >> 2, u = lin & 3;
            unsigned doff = (unsigned)(r * 80 + u * 16);
            asm volatile("cp.async.cg.shared.global [%0], [%1], 16;"
                :: "r"(ab + doff), "l"(&g_qn[(size_t)(n0 + r) * DDIM + u * 8]));
            asm volatile("cp.async.cg.shared.global [%0], [%1], 16;"
                :: "r"(bb + doff), "l"(&g_patn[(size_t)(g0 + r) * DDIM + u * 8]));
        }
        asm volatile("cp.async.commit_group;");
    }

    for (int kt = 0; kt < 32; kt++) {
        int buf = kt & 1;
        if (kt < 31) {
            unsigned ab = smb + (buf ^ 1) * STG_BYTES, bb = ab + OP_BYTES;
            int k0 = (kt + 1) * 32;
            #pragma unroll
            for (int j = 0; j < 2; j++) {
                int lin = j * 256 + tid, r = lin >> 2, u = lin & 3;
                unsigned doff = (unsigned)(r * 80 + u * 16);
                asm volatile("cp.async.cg.shared.global [%0], [%1], 16;"
                    :: "r"(ab + doff), "l"(&g_qn[(size_t)(n0 + r) * DDIM + k0 + u * 8]));
                asm volatile("cp.async.cg.shared.global [%0], [%1], 16;"
                    :: "r"(bb + doff), "l"(&g_patn[(size_t)(g0 + r) * DDIM + k0 + u * 8]));
            }
            asm volatile("cp.async.commit_group;");
            asm volatile("cp.async.wait_group 1;");
        } else {
            asm volatile("cp.async.wait_group 0;");
        }
        __syncthreads();

        unsigned ab = smb + buf * STG_BYTES, bb = ab + OP_BYTES;
        #pragma unroll
        for (int ks = 0; ks < 2; ks++) {
            unsigned a[2][4];
            #pragma unroll
            for (int mt = 0; mt < 2; mt++)
                ldsm4(a[mt], ab + (unsigned)(((wm * 32 + mt * 16 + a_row) * SA1 + ks * 16 + a_col) * 2));
            #pragma unroll
            for (int nt2 = 0; nt2 < 4; nt2++) {
                unsigned b[4];
                ldsm4(b, bb + (unsigned)(((wn * 64 + nt2 * 16 + b_row) * SA1 + ks * 16 + b_col) * 2));
                #pragma unroll
                for (int mt = 0; mt < 2; mt++) {
                    mma16816(c[mt][nt2 * 2],     a[mt], b[0], b[1]);
                    mma16816(c[mt][nt2 * 2 + 1], a[mt], b[2], b[3]);
                }
            }
        }
        __syncthreads();
    }

    float mst = g_mstar;
    #pragma unroll
    for (int mt = 0; mt < 2; mt++) {
        int r1 = wm * 32 + mt * 16 + gr, r2 = r1 + 8;
        float rs1 = 0.f, rs2 = 0.f;
        #pragma unroll
        for (int nt = 0; nt < 8; nt++) {
            int col = wn * 64 + nt * 8 + 2 * tig;
            float2 hh = *(const float2*)&g_h[g0 + col];
            float e0 = __expf((c[mt][nt][0] - hh.x) * INV_TEMP - mst);
            float e1 = __expf((c[mt][nt][1] - hh.y) * INV_TEMP - mst);
            float e2 = __expf((c[mt][nt][2] - hh.x) * INV_TEMP - mst);
            float e3 = __expf((c[mt][nt][3] - hh.y) * INV_TEMP - mst);
            size_t o1 = (size_t)(n0 + r1) * GDIM + g0 + col;
            size_t o2 = (size_t)(n0 + r2) * GDIM + g0 + col;
            *(float2*)&outW[o1] = make_float2(e0, e1);
            *(float2*)&outW[o2] = make_float2(e2, e3);
            *(__nv_bfloat162*)&g_we[o1] = __floats2bfloat162_rn(e0, e1);
            *(__nv_bfloat162*)&g_we[o2] = __floats2bfloat162_rn(e2, e3);
            rs1 += e0 + e1; rs2 += e2 + e3;
        }
        rs1 += __shfl_xor_sync(0xffffffffu, rs1, 1);
        rs1 += __shfl_xor_sync(0xffffffffu, rs1, 2);
        rs2 += __shfl_xor_sync(0xffffffffu, rs2, 1);
        rs2 += __shfl_xor_sync(0xffffffffu, rs2, 2);
        if (tig == 0) { smrow[wn][r1] = rs1; smrow[wn][r2] = rs2; }
    }
    __syncthreads();
    if (tid < 128)
        g_rowpart[(size_t)blockIdx.x * N_ROWS + n0 + tid] = smrow[0][tid] + smrow[1][tid];
}

// ---------------- rowsum reduce (32 g-tiles) + scale flat into bf16 ----------------
__global__ void __launch_bounds__(256) scale_flat(const float* __restrict__ pe) {
    int row = blockIdx.x, t = threadIdx.x;
    __shared__ float sinv;
    if (t < 32) {
        float v = g_rowpart[(size_t)t * N_ROWS + row];
        #pragma unroll
        for (int o = 16; o > 0; o >>= 1) v += __shfl_xor_sync(0xffffffffu, v, o);
        if (t == 0) {
            float iv = 1.0f / fmaxf(v, 1e-30f);
            g_invrs[row] = iv;
            sinv = iv;
        }
    }
    __syncthreads();
    float iv = sinv;
    float4 v = ((const float4*)(pe + (size_t)row * DDIM))[t];
    size_t base = (size_t)row * DDIM + (size_t)t * 4;
    *(__nv_bfloat162*)&g_flatb[base]     = __floats2bfloat162_rn(v.x*iv, v.y*iv);
    *(__nv_bfloat162*)&g_flatb[base + 2] = __floats2bfloat162_rn(v.z*iv, v.w*iv);
}

// ---------------- normalize W in place (fp32), emit column partials ----------------
__global__ void __launch_bounds__(256) normalize_k(float* __restrict__ W) {
    int tid = threadIdx.x;
    int c0 = blockIdx.x * 1024 + tid * 4;
    int r0 = blockIdx.y * 64;
    __shared__ float invs[64];
    if (tid < 64) invs[tid] = g_invrs[r0 + tid];
    __syncthreads();
    float cs0 = 0.f, cs1 = 0.f, cs2 = 0.f, cs3 = 0.f;
    for (int r = 0; r < 64; r++) {
        size_t off = (size_t)(r0 + r) * GDIM + c0;
        float4 e = *(float4*)&W[off];
        float iv = invs[r];
        e.x *= iv; e.y *= iv; e.z *= iv; e.w *= iv;
        *(float4*)&W[off] = e;
        cs0 += e.x; cs1 += e.y; cs2 += e.z; cs3 += e.w;
    }
    *(float4*)&g_colpart[(size_t)blockIdx.y * GDIM + c0] = make_float4(cs0, cs1, cs2, cs3);
}

// ---------------- GEMM2: updates = E^T @ flat_scaled, split-K=4, ldmatrix.trans ----------------
__global__ void __launch_bounds__(256) gemm2_k() {
    __shared__ __align__(16) __nv_bfloat16 As[32 * 136];
    __shared__ __align__(16) __nv_bfloat16 Bs[32 * 136];
    int tid = threadIdx.x;
    int w = tid >> 5, lane = tid & 31;
    int wm = w >> 1, wn = w & 1;
    int gr = lane >> 2, tig = lane & 3;
    int d0 = blockIdx.x * 128, g0 = blockIdx.y * 128;
    int kbase = blockIdx.z * 4096;

    unsigned as_base = (unsigned)__cvta_generic_to_shared(As);
    unsigned bs_base = (unsigned)__cvta_generic_to_shared(Bs);

    int a_k = (lane & 7) + ((lane >> 4) << 3);
    int a_m = ((lane >> 3) & 1) << 3;
    int b_k = (lane & 7) + (((lane >> 3) & 1) << 3);
    int b_d = (lane >> 4) << 3;

    int crow = tid >> 4;
    int cu = tid & 15;

    float c[2][8][4];
    #pragma unroll
    for (int a = 0; a < 2; a++)
        #pragma unroll
        for (int b = 0; b < 8; b++)
            #pragma unroll
            for (int d = 0; d < 4; d++) c[a][b][d] = 0.f;

    uint4 ra[2], rb[2];
    #pragma unroll
    for (int j = 0; j < 2; j++) {
        int row = j * 16 + crow;
        ra[j] = *(const uint4*)&g_we[(size_t)(kbase + row) * GDIM + g0 + cu * 8];
        rb[j] = *(const uint4*)&g_flatb[(size_t)(kbase + row) * DDIM + d0 + cu * 8];
    }

    for (int kt = 0; kt < 128; kt++) {
        #pragma unroll
        for (int j = 0; j < 2; j++) {
            int row = j * 16 + crow;
            *(uint4*)&As[row * 136 + cu * 8] = ra[j];
            *(uint4*)&Bs[row * 136 + cu * 8] = rb[j];
        }
        __syncthreads();
        if (kt < 127) {
            int k0 = kbase + (kt + 1) * 32;
            #pragma unroll
            for (int j = 0; j < 2; j++) {
                int row = j * 16 + crow;
                ra[j] = *(const uint4*)&g_we[(size_t)(k0 + row) * GDIM + g0 + cu * 8];
                rb[j] = *(const uint4*)&g_flatb[(size_t)(k0 + row) * DDIM + d0 + cu * 8];
            }
        }
        #pragma unroll
        for (int ks = 0; ks < 2; ks++) {
            unsigned a[2][4];
            #pragma unroll
            for (int mt = 0; mt < 2; mt++)
                ldsm4t(a[mt], as_base + (unsigned)(((ks * 16 + a_k) * 136 + wm * 32 + mt * 16 + a_m) * 2));
            #pragma unroll
            for (int nt2 = 0; nt2 < 4; nt2++) {
                unsigned b[4];
                ldsm4t(b, bs_base + (unsigned)(((ks * 16 + b_k) * 136 + wn * 64 + nt2 * 16 + b_d) * 2));
                #pragma unroll
                for (int mt = 0; mt < 2; mt++) {
                    mma16816(c[mt][nt2 * 2],     a[mt], b[0], b[1]);
                    mma16816(c[mt][nt2 * 2 + 1], a[mt], b[2], b[3]);
                }
            }
        }
        __syncthreads();
    }

    float* dst = g_upd[blockIdx.z];
    #pragma unroll
    for (int mt = 0; mt < 2; mt++) {
        int r1 = wm * 32 + mt * 16 + gr, r2 = r1 + 8;
        #pragma unroll
        for (int nt = 0; nt < 8; nt++) {
            int col = wn * 64 + nt * 8 + 2 * tig;
            *(float2*)&dst[(size_t)(g0 + r1) * DDIM + d0 + col] = make_float2(c[mt][nt][0], c[mt][nt][1]);
            *(float2*)&dst[(size_t)(g0 + r2) * DDIM + d0 + col] = make_float2(c[mt][nt][2], c[mt][nt][3]);
        }
    }
}

// ---------------- wsum reduction ----------------
__global__ void __launch_bounds__(256) wsum_reduce_k() {
    int g = blockIdx.x * 256 + threadIdx.x;
    float s = 0.f;
    for (int b = 0; b < 256; b++) s += g_colpart[(size_t)b * GDIM + g];
    g_wsum[g] = s;
}

// ---------------- final: blend, renormalize patterns, usage update ----------------
__global__ void __launch_bounds__(256) final_k(const float* __restrict__ patterns,
                                               const float* __restrict__ usage,
                                               float* __restrict__ out) {
    int g = blockIdx.x, t = threadIdx.x;
    __shared__ float sm8[8];
    size_t base = (size_t)g * DDIM + (size_t)t * 4;
    float4 r0 = *(const float4*)&g_upd[0][base];
    float4 r1 = *(const float4*)&g_upd[1][base];
    float4 r2 = *(const float4*)&g_upd[2][base];
    float4 r3 = *(const float4*)&g_upd[3][base];
    float4 raw;
    raw.x = (r0.x + r1.x) + (r2.x + r3.x);
    raw.y = (r0.y + r1.y) + (r2.y + r3.y);
    raw.z = (r0.z + r1.z) + (r2.z + r3.z);
    raw.w = (r0.w + r1.w) + (r2.w + r3.w);
    float ws = g_wsum[g];
    float sc = OMDEC / (ws + EPSF);
    float4 p = *(const float4*)&patterns[base];
    float4 v;
    v.x = p.x * DECAYF + raw.x * sc;
    v.y = p.y * DECAYF + raw.y * sc;
    v.z = p.z * DECAYF + raw.z * sc;
    v.w = p.w * DECAYF + raw.w * sc;
    float ss = v.x*v.x + v.y*v.y + v.z*v.z + v.w*v.w;
    float tot = block_sum_256(ss, sm8);
    float inv = 1.0f / fmaxf(sqrtf(tot), 1e-12f);
    bool valid = ws > 0.0f;
    float4 o;
    o.x = valid ? v.x * inv : p.x;
    o.y = valid ? v.y * inv : p.y;
    o.z = valid ? v.z * inv : p.z;
    o.w = valid ? v.w * inv : p.w;
    *(float4*)&out[(size_t)P_OFF + base] = o;
    if (t == 0)
        out[(size_t)U_OFF + g] = usage[g] * DECAYF + (valid ? OMDEC * ws : 0.0f);
}

// ---------------- launch ----------------
extern "C" void kernel_launch(void* const* d_in, const int* in_sizes, int n_in,
                              void* d_out, int out_size) {
    (void)in_sizes; (void)n_in; (void)out_size;
    const float* pe       = (const float*)d_in[0];
    const float* patterns = (const float*)d_in[1];
    const float* usage    = (const float*)d_in[2];
    float* out = (float*)d_out;

    prep_rows<<<N_ROWS, 256>>>(pe);
    prep_pat<<<GDIM, 256>>>(patterns);
    prep_h<<<1, 1024>>>(usage);
    gemm1_softmax<<<dim3(32, 128), 256>>>(out);
    scale_flat<<<N_ROWS, 256>>>(pe);
    gemm2_k<<<dim3(8, 32, 4), 256>>>();
    normalize_k<<<dim3(4, 256), 256>>>(out);
    wsum_reduce_k<<<16, 256>>>();
    final_k<<<GDIM, 256>>>(patterns, usage, out);
}

// round 16
// speedup vs baseline: 1.6464x; 1.0411x over previous
#include <cuda_runtime.h>
#include <cuda_bf16.h>

#define N_ROWS 16384
#define DDIM   1024
#define GDIM   4096
#define DECAYF 0.97f
#define OMDEC  0.03f
#define INV_TEMP (1.0f/0.7f)
#define EPSF 1e-6f

#define P_OFF  67108864      // N_ROWS*GDIM
#define U_OFF  71303168      // P_OFF + GDIM*DDIM

// ---------------- device scratch (static; no allocations) ----------------
static __device__ __align__(16) __nv_bfloat16 g_qn[(size_t)N_ROWS * DDIM];     // normalized queries
static __device__ __align__(16) __nv_bfloat16 g_flatb[(size_t)N_ROWS * DDIM];  // flat * inv_rowsum (bf16)
static __device__ __align__(16) __nv_bfloat16 g_patn[(size_t)GDIM * DDIM];     // normalized patterns
static __device__ __align__(16) __nv_bfloat16 g_we[(size_t)N_ROWS * GDIM];     // exp logits (bf16, unnormalized)
static __device__ __align__(16) float g_upd[4][(size_t)GDIM * DDIM];           // split-K partials
static __device__ __align__(16) float g_rowpart[(size_t)32 * N_ROWS];          // per-gtile row sums
static __device__ __align__(16) float g_colpart[(size_t)256 * GDIM];           // per-rowblock col sums
static __device__ __align__(16) float g_invrs[N_ROWS];                         // 1/rowsum
static __device__ __align__(16) float g_h[GDIM];
static __device__ __align__(16) float g_wsum[GDIM];
static __device__ float g_mstar;

// ---------------- helpers ----------------
__device__ __forceinline__ void mma16816(float* c, const unsigned* a, unsigned b0, unsigned b1) {
    asm volatile(
        "mma.sync.aligned.m16n8k16.row.col.f32.bf16.bf16.f32 "
        "{%0,%1,%2,%3}, {%4,%5,%6,%7}, {%8,%9}, {%0,%1,%2,%3};\n"
        : "+f"(c[0]), "+f"(c[1]), "+f"(c[2]), "+f"(c[3])
        : "r"(a[0]), "r"(a[1]), "r"(a[2]), "r"(a[3]), "r"(b0), "r"(b1));
}

__device__ __forceinline__ void ldsm4(unsigned* r, unsigned addr) {
    asm volatile("ldmatrix.sync.aligned.m8n8.x4.shared.b16 {%0,%1,%2,%3}, [%4];"
        : "=r"(r[0]), "=r"(r[1]), "=r"(r[2]), "=r"(r[3]) : "r"(addr));
}

__device__ __forceinline__ void ldsm4t(unsigned* r, unsigned addr) {
    asm volatile("ldmatrix.sync.aligned.m8n8.x4.trans.shared.b16 {%0,%1,%2,%3}, [%4];"
        : "=r"(r[0]), "=r"(r[1]), "=r"(r[2]), "=r"(r[3]) : "r"(addr));
}

__device__ __forceinline__ float block_sum_256(float v, float* sm8) {
    int t = threadIdx.x;
    #pragma unroll
    for (int o = 16; o > 0; o >>= 1) v += __shfl_xor_sync(0xffffffffu, v, o);
    if ((t & 31) == 0) sm8[t >> 5] = v;
    __syncthreads();
    float tot = 0.f;
    #pragma unroll
    for (int i = 0; i < 8; i++) tot += sm8[i];
    return tot;
}

// ---------------- prep kernels ----------------
__global__ void __launch_bounds__(256) prep_rows(const float* __restrict__ pe) {
    int row = blockIdx.x, t = threadIdx.x;
    __shared__ float sm8[8];
    float4 v = ((const float4*)(pe + (size_t)row * DDIM))[t];
    float ss = v.x*v.x + v.y*v.y + v.z*v.z + v.w*v.w;
    float tot = block_sum_256(ss, sm8);
    float inv = 1.0f / fmaxf(sqrtf(tot), 1e-12f);
    size_t base = (size_t)row * DDIM + (size_t)t * 4;
    *(__nv_bfloat162*)&g_qn[base]     = __floats2bfloat162_rn(v.x*inv, v.y*inv);
    *(__nv_bfloat162*)&g_qn[base + 2] = __floats2bfloat162_rn(v.z*inv, v.w*inv);
}

__global__ void __launch_bounds__(256) prep_pat(const float* __restrict__ pat) {
    int row = blockIdx.x, t = threadIdx.x;
    __shared__ float sm8[8];
    float4 v = ((const float4*)(pat + (size_t)row * DDIM))[t];
    float ss = v.x*v.x + v.y*v.y + v.z*v.z + v.w*v.w;
    float tot = block_sum_256(ss, sm8);
    float inv = 1.0f / fmaxf(sqrtf(tot), 1e-12f);
    size_t base = (size_t)row * DDIM + (size_t)t * 4;
    *(__nv_bfloat162*)&g_patn[base]     = __floats2bfloat162_rn(v.x*inv, v.y*inv);
    *(__nv_bfloat162*)&g_patn[base + 2] = __floats2bfloat162_rn(v.z*inv, v.w*inv);
}

__global__ void __launch_bounds__(1024) prep_h(const float* __restrict__ usage) {
    int t = threadIdx.x;
    __shared__ float sm[32];
    float4 u = ((const float4*)usage)[t];
    float4 h;
    h.x = logf(fmaxf(u.x, EPSF)); h.y = logf(fmaxf(u.y, EPSF));
    h.z = logf(fmaxf(u.z, EPSF)); h.w = logf(fmaxf(u.w, EPSF));
    ((float4*)g_h)[t] = h;
    float m = fmaxf(fmaxf(1.f - h.x, 1.f - h.y), fmaxf(1.f - h.z, 1.f - h.w)) * INV_TEMP;
    #pragma unroll
    for (int o = 16; o > 0; o >>= 1) m = fmaxf(m, __shfl_xor_sync(0xffffffffu, m, o));
    if ((t & 31) == 0) sm[t >> 5] = m;
    __syncthreads();
    if (t == 0) {
        float mm = sm[0];
        #pragma unroll
        for (int i = 1; i < 32; i++) mm = fmaxf(mm, sm[i]);
        g_mstar = mm;
    }
}

// ---------------- GEMM1: 128x128 CTA tile, 256 thr, 32x64 warp tiles,
//                  SA1=40 padded smem (conflict-free), cp.async double-buffered ----------------
#define SA1 40              // row stride (elems): 80B -> conflict-free (20r mod 32 banks)
#define OP_BYTES 10240      // 128 rows * 80B
#define STG_BYTES 20480     // A + B per stage
__global__ void __launch_bounds__(256) gemm1_softmax(float* __restrict__ outW) {
    __shared__ __align__(16) char smbuf[2 * STG_BYTES];   // 40KB
    __shared__ float smrow[2][128];
    int tid = threadIdx.x;
    int w = tid >> 5, lane = tid & 31;
    int wm = w >> 1, wn = w & 1;
    int gr = lane >> 2, tig = lane & 3;
    int n0 = blockIdx.y * 128, g0 = blockIdx.x * 128;

    unsigned smb = (unsigned)__cvta_generic_to_shared(smbuf);

    // ldmatrix lane maps (R7-verified)
    int a_row = lane & 15;
    int a_col = (lane >> 4) << 3;
    int b_row = ((lane >> 4) << 3) + (lane & 7);
    int b_col = ((lane >> 3) & 1) << 3;

    float c[2][8][4];
    #pragma unroll
    for (int a = 0; a < 2; a++)
        #pragma unroll
        for (int b = 0; b < 8; b++)
            #pragma unroll
            for (int d = 0; d < 4; d++) c[a][b][d] = 0.f;

    // prologue: stage 0
    {
        unsigned ab = smb, bb = smb + OP_BYTES;
        #pragma unroll
        for (int j = 0; j < 2; j++) {
            int lin = j * 256 + tid, r = lin >> 2, u = lin & 3;
            unsigned doff = (unsigned)(r * 80 + u * 16);
            asm volatile("cp.async.cg.shared.global [%0], [%1], 16;"
                :: "r"(ab + doff), "l"(&g_qn[(size_t)(n0 + r) * DDIM + u * 8]));
            asm volatile("cp.async.cg.shared.global [%0], [%1], 16;"
                :: "r"(bb + doff), "l"(&g_patn[(size_t)(g0 + r) * DDIM + u * 8]));
        }
        asm volatile("cp.async.commit_group;");
    }

    for (int kt = 0; kt < 32; kt++) {
        int buf = kt & 1;
        if (kt < 31) {
            unsigned ab = smb + (buf ^ 1) * STG_BYTES, bb = ab + OP_BYTES;
            int k0 = (kt + 1) * 32;
            #pragma unroll
            for (int j = 0; j < 2; j++) {
                int lin = j * 256 + tid, r = lin >> 2, u = lin & 3;
                unsigned doff = (unsigned)(r * 80 + u * 16);
                asm volatile("cp.async.cg.shared.global [%0], [%1], 16;"
                    :: "r"(ab + doff), "l"(&g_qn[(size_t)(n0 + r) * DDIM + k0 + u * 8]));
                asm volatile("cp.async.cg.shared.global [%0], [%1], 16;"
                    :: "r"(bb + doff), "l"(&g_patn[(size_t)(g0 + r) * DDIM + k0 + u * 8]));
            }
            asm volatile("cp.async.commit_group;");
            asm volatile("cp.async.wait_group 1;");
        } else {
            asm volatile("cp.async.wait_group 0;");
        }
        __syncthreads();

        unsigned ab = smb + buf * STG_BYTES, bb = ab + OP_BYTES;
        #pragma unroll
        for (int ks = 0; ks < 2; ks++) {
            unsigned a[2][4];
            #pragma unroll
            for (int mt = 0; mt < 2; mt++)
                ldsm4(a[mt], ab + (unsigned)(((wm * 32 + mt * 16 + a_row) * SA1 + ks * 16 + a_col) * 2));
            #pragma unroll
            for (int nt2 = 0; nt2 < 4; nt2++) {
                unsigned b[4];
                ldsm4(b, bb + (unsigned)(((wn * 64 + nt2 * 16 + b_row) * SA1 + ks * 16 + b_col) * 2));
                #pragma unroll
                for (int mt = 0; mt < 2; mt++) {
                    mma16816(c[mt][nt2 * 2],     a[mt], b[0], b[1]);
                    mma16816(c[mt][nt2 * 2 + 1], a[mt], b[2], b[3]);
                }
            }
        }
        __syncthreads();
    }

    float mst = g_mstar;
    #pragma unroll
    for (int mt = 0; mt < 2; mt++) {
        int r1 = wm * 32 + mt * 16 + gr, r2 = r1 + 8;
        float rs1 = 0.f, rs2 = 0.f;
        #pragma unroll
        for (int nt = 0; nt < 8; nt++) {
            int col = wn * 64 + nt * 8 + 2 * tig;
            float2 hh = *(const float2*)&g_h[g0 + col];
            float e0 = __expf((c[mt][nt][0] - hh.x) * INV_TEMP - mst);
            float e1 = __expf((c[mt][nt][1] - hh.y) * INV_TEMP - mst);
            float e2 = __expf((c[mt][nt][2] - hh.x) * INV_TEMP - mst);
            float e3 = __expf((c[mt][nt][3] - hh.y) * INV_TEMP - mst);
            size_t o1 = (size_t)(n0 + r1) * GDIM + g0 + col;
            size_t o2 = (size_t)(n0 + r2) * GDIM + g0 + col;
            *(float2*)&outW[o1] = make_float2(e0, e1);
            *(float2*)&outW[o2] = make_float2(e2, e3);
            *(__nv_bfloat162*)&g_we[o1] = __floats2bfloat162_rn(e0, e1);
            *(__nv_bfloat162*)&g_we[o2] = __floats2bfloat162_rn(e2, e3);
            rs1 += e0 + e1; rs2 += e2 + e3;
        }
        rs1 += __shfl_xor_sync(0xffffffffu, rs1, 1);
        rs1 += __shfl_xor_sync(0xffffffffu, rs1, 2);
        rs2 += __shfl_xor_sync(0xffffffffu, rs2, 1);
        rs2 += __shfl_xor_sync(0xffffffffu, rs2, 2);
        if (tig == 0) { smrow[wn][r1] = rs1; smrow[wn][r2] = rs2; }
    }
    __syncthreads();
    if (tid < 128)
        g_rowpart[(size_t)blockIdx.x * N_ROWS + n0 + tid] = smrow[0][tid] + smrow[1][tid];
}

// ---------------- rowsum reduce (32 g-tiles) + scale flat into bf16 ----------------
__global__ void __launch_bounds__(256) scale_flat(const float* __restrict__ pe) {
    int row = blockIdx.x, t = threadIdx.x;
    __shared__ float sinv;
    if (t < 32) {
        float v = g_rowpart[(size_t)t * N_ROWS + row];
        #pragma unroll
        for (int o = 16; o > 0; o >>= 1) v += __shfl_xor_sync(0xffffffffu, v, o);
        if (t == 0) {
            float iv = 1.0f / fmaxf(v, 1e-30f);
            g_invrs[row] = iv;
            sinv = iv;
        }
    }
    __syncthreads();
    float iv = sinv;
    float4 v = ((const float4*)(pe + (size_t)row * DDIM))[t];
    size_t base = (size_t)row * DDIM + (size_t)t * 4;
    *(__nv_bfloat162*)&g_flatb[base]     = __floats2bfloat162_rn(v.x*iv, v.y*iv);
    *(__nv_bfloat162*)&g_flatb[base + 2] = __floats2bfloat162_rn(v.z*iv, v.w*iv);
}

// ---------------- normalize W in place (fp32), emit column partials ----------------
__global__ void __launch_bounds__(256) normalize_k(float* __restrict__ W) {
    int tid = threadIdx.x;
    int c0 = blockIdx.x * 1024 + tid * 4;
    int r0 = blockIdx.y * 64;
    __shared__ float invs[64];
    if (tid < 64) invs[tid] = g_invrs[r0 + tid];
    __syncthreads();
    float cs0 = 0.f, cs1 = 0.f, cs2 = 0.f, cs3 = 0.f;
    for (int r = 0; r < 64; r++) {
        size_t off = (size_t)(r0 + r) * GDIM + c0;
        float4 e = *(float4*)&W[off];
        float iv = invs[r];
        e.x *= iv; e.y *= iv; e.z *= iv; e.w *= iv;
        *(float4*)&W[off] = e;
        cs0 += e.x; cs1 += e.y; cs2 += e.z; cs3 += e.w;
    }
    *(float4*)&g_colpart[(size_t)blockIdx.y * GDIM + c0] = make_float4(cs0, cs1, cs2, cs3);
}

// ---------------- GEMM2: updates = E^T @ flat_scaled, split-K=4,
//                  cp.async double-buffered, 272B-row tiles, ldmatrix.trans ----------------
#define G2_OP  8704         // 32 rows * 272B
#define G2_STG 17408        // A + B per stage
__global__ void __launch_bounds__(256) gemm2_k() {
    __shared__ __align__(16) char smbuf2[2 * G2_STG];    // 34KB
    int tid = threadIdx.x;
    int w = tid >> 5, lane = tid & 31;
    int wm = w >> 1, wn = w & 1;
    int gr = lane >> 2, tig = lane & 3;
    int d0 = blockIdx.x * 128, g0 = blockIdx.y * 128;
    int kbase = blockIdx.z * 4096;

    unsigned smb = (unsigned)__cvta_generic_to_shared(smbuf2);

    int a_k = (lane & 7) + ((lane >> 4) << 3);
    int a_m = ((lane >> 3) & 1) << 3;
    int b_k = (lane & 7) + (((lane >> 3) & 1) << 3);
    int b_d = (lane >> 4) << 3;

    // copy map: 512 16B-chunks per operand; thread does 2 (row = j*16 + tid>>4, u = tid&15)
    int crow = tid >> 4, cu = tid & 15;

    float c[2][8][4];
    #pragma unroll
    for (int a = 0; a < 2; a++)
        #pragma unroll
        for (int b = 0; b < 8; b++)
            #pragma unroll
            for (int d = 0; d < 4; d++) c[a][b][d] = 0.f;

    // prologue: stage 0
    {
        unsigned ab = smb, bb = smb + G2_OP;
        #pragma unroll
        for (int j = 0; j < 2; j++) {
            int row = j * 16 + crow;
            unsigned doff = (unsigned)(row * 272 + cu * 16);
            asm volatile("cp.async.cg.shared.global [%0], [%1], 16;"
                :: "r"(ab + doff), "l"(&g_we[(size_t)(kbase + row) * GDIM + g0 + cu * 8]));
            asm volatile("cp.async.cg.shared.global [%0], [%1], 16;"
                :: "r"(bb + doff), "l"(&g_flatb[(size_t)(kbase + row) * DDIM + d0 + cu * 8]));
        }
        asm volatile("cp.async.commit_group;");
    }

    for (int kt = 0; kt < 128; kt++) {
        int buf = kt & 1;
        if (kt < 127) {
            unsigned ab = smb + (buf ^ 1) * G2_STG, bb = ab + G2_OP;
            int k0 = kbase + (kt + 1) * 32;
            #pragma unroll
            for (int j = 0; j < 2; j++) {
                int row = j * 16 + crow;
                unsigned doff = (unsigned)(row * 272 + cu * 16);
                asm volatile("cp.async.cg.shared.global [%0], [%1], 16;"
                    :: "r"(ab + doff), "l"(&g_we[(size_t)(k0 + row) * GDIM + g0 + cu * 8]));
                asm volatile("cp.async.cg.shared.global [%0], [%1], 16;"
                    :: "r"(bb + doff), "l"(&g_flatb[(size_t)(k0 + row) * DDIM + d0 + cu * 8]));
            }
            asm volatile("cp.async.commit_group;");
            asm volatile("cp.async.wait_group 1;");
        } else {
            asm volatile("cp.async.wait_group 0;");
        }
        __syncthreads();

        unsigned ab = smb + buf * G2_STG, bb = ab + G2_OP;
        #pragma unroll
        for (int ks = 0; ks < 2; ks++) {
            unsigned a[2][4];
            #pragma unroll
            for (int mt = 0; mt < 2; mt++)
                ldsm4t(a[mt], ab + (unsigned)(((ks * 16 + a_k) * 136 + wm * 32 + mt * 16 + a_m) * 2));
            #pragma unroll
            for (int nt2 = 0; nt2 < 4; nt2++) {
                unsigned b[4];
                ldsm4t(b, bb + (unsigned)(((ks * 16 + b_k) * 136 + wn * 64 + nt2 * 16 + b_d) * 2));
                #pragma unroll
                for (int mt = 0; mt < 2; mt++) {
                    mma16816(c[mt][nt2 * 2],     a[mt], b[0], b[1]);
                    mma16816(c[mt][nt2 * 2 + 1], a[mt], b[2], b[3]);
                }
            }
        }
        __syncthreads();
    }

    float* dst = g_upd[blockIdx.z];
    #pragma unroll
    for (int mt = 0; mt < 2; mt++) {
        int r1 = wm * 32 + mt * 16 + gr, r2 = r1 + 8;
        #pragma unroll
        for (int nt = 0; nt < 8; nt++) {
            int col = wn * 64 + nt * 8 + 2 * tig;
            *(float2*)&dst[(size_t)(g0 + r1) * DDIM + d0 + col] = make_float2(c[mt][nt][0], c[mt][nt][1]);
            *(float2*)&dst[(size_t)(g0 + r2) * DDIM + d0 + col] = make_float2(c[mt][nt][2], c[mt][nt][3]);
        }
    }
}

// ---------------- wsum reduction ----------------
__global__ void __launch_bounds__(256) wsum_reduce_k() {
    int g = blockIdx.x * 256 + threadIdx.x;
    float s = 0.f;
    for (int b = 0; b < 256; b++) s += g_colpart[(size_t)b * GDIM + g];
    g_wsum[g] = s;
}

// ---------------- final: blend, renormalize patterns, usage update ----------------
__global__ void __launch_bounds__(256) final_k(const float* __restrict__ patterns,
                                               const float* __restrict__ usage,
                                               float* __restrict__ out) {
    int g = blockIdx.x, t = threadIdx.x;
    __shared__ float sm8[8];
    size_t base = (size_t)g * DDIM + (size_t)t * 4;
    float4 r0 = *(const float4*)&g_upd[0][base];
    float4 r1 = *(const float4*)&g_upd[1][base];
    float4 r2 = *(const float4*)&g_upd[2][base];
    float4 r3 = *(const float4*)&g_upd[3][base];
    float4 raw;
    raw.x = (r0.x + r1.x) + (r2.x + r3.x);
    raw.y = (r0.y + r1.y) + (r2.y + r3.y);
    raw.z = (r0.z + r1.z) + (r2.z + r3.z);
    raw.w = (r0.w + r1.w) + (r2.w + r3.w);
    float ws = g_wsum[g];
    float sc = OMDEC / (ws + EPSF);
    float4 p = *(const float4*)&patterns[base];
    float4 v;
    v.x = p.x * DECAYF + raw.x * sc;
    v.y = p.y * DECAYF + raw.y * sc;
    v.z = p.z * DECAYF + raw.z * sc;
    v.w = p.w * DECAYF + raw.w * sc;
    float ss = v.x*v.x + v.y*v.y + v.z*v.z + v.w*v.w;
    float tot = block_sum_256(ss, sm8);
    float inv = 1.0f / fmaxf(sqrtf(tot), 1e-12f);
    bool valid = ws > 0.0f;
    float4 o;
    o.x = valid ? v.x * inv : p.x;
    o.y = valid ? v.y * inv : p.y;
    o.z = valid ? v.z * inv : p.z;
    o.w = valid ? v.w * inv : p.w;
    *(float4*)&out[(size_t)P_OFF + base] = o;
    if (t == 0)
        out[(size_t)U_OFF + g] = usage[g] * DECAYF + (valid ? OMDEC * ws : 0.0f);
}

// ---------------- launch ----------------
extern "C" void kernel_launch(void* const* d_in, const int* in_sizes, int n_in,
                              void* d_out, int out_size) {
    (void)in_sizes; (void)n_in; (void)out_size;
    const float* pe       = (const float*)d_in[0];
    const float* patterns = (const float*)d_in[1];
    const float* usage    = (const float*)d_in[2];
    float* out = (float*)d_out;

    prep_rows<<<N_ROWS, 256>>>(pe);
    prep_pat<<<GDIM, 256>>>(patterns);
    prep_h<<<1, 1024>>>(usage);
    gemm1_softmax<<<dim3(32, 128), 256>>>(out);
    scale_flat<<<N_ROWS, 256>>>(pe);
    gemm2_k<<<dim3(8, 32, 4), 256>>>();
    normalize_k<<<dim3(4, 256), 256>>>(out);
    wsum_reduce_k<<<16, 256>>>();
    final_k<<<GDIM, 256>>>(patterns, usage, out);
}